// round 8
// baseline (speedup 1.0000x reference)
#include <cuda_runtime.h>
#include <cstdint>

// YoloLoss: y (16384,7,7,30) f32, gt same -> scalar f32.
// Pure HBM-bound reduction: 192.7 MB read, 4 B written.

#define LAMBDA_COORD 5.0f
#define LAMBDA_NOOBJ 0.5f

static constexpr int B_SZ   = 16384;
static constexpr int NCELL  = 16384 * 7 * 7;   // 802816
static constexpr int TPB    = 256;
static constexpr int NBLK   = NCELL / TPB;      // 3136 exactly, no tail

// Scratch for deterministic two-pass reduction (no allocations allowed).
__device__ double g_partials[NBLK];

__device__ __forceinline__ float iou_f(float x1, float y1, float w1, float h1,
                                       float x2, float y2, float w2, float h2) {
    float xl = fmaxf(x1 - 0.5f * w1, x2 - 0.5f * w2);
    float yt = fmaxf(y1 - 0.5f * h1, y2 - 0.5f * h2);
    float xr = fminf(x1 + 0.5f * w1, x2 + 0.5f * w2);
    float yb = fminf(y1 + 0.5f * h1, y2 + 0.5f * h2);
    bool valid = (xr >= xl) && (yb >= yt);
    float inter = (xr - xl) * (yb - yt);
    float uni = w1 * h1 + w2 * h2 - inter;
    float safe = (uni == 0.0f) ? 1.0f : uni;
    return valid ? (inter / safe) : 0.0f;
}

__global__ __launch_bounds__(TPB) void yolo_cell_kernel(
    const float* __restrict__ y, const float* __restrict__ gt)
{
    const int c = blockIdx.x * TPB + threadIdx.x;   // one cell per thread

    // 30 floats per cell = 120 B, 8-byte aligned for every cell -> float2 loads.
    const float2* __restrict__ yp = reinterpret_cast<const float2*>(y)  + (size_t)c * 15;
    const float2* __restrict__ tp = reinterpret_cast<const float2*>(gt) + (size_t)c * 15;

    float p[30], t[30];
#pragma unroll
    for (int i = 0; i < 15; i++) { float2 v = yp[i]; p[2*i] = v.x; p[2*i+1] = v.y; }
#pragma unroll
    for (int i = 0; i < 15; i++) { float2 v = tp[i]; t[2*i] = v.x; t[2*i+1] = v.y; }

    const float obj   = (t[4] > 0.0f)  ? 1.0f : 0.0f;
    const float noobj = (t[4] == 0.0f) ? 1.0f : 0.0f;   // NOT 1-obj: matches reference

    // class loss: obj * sum_{d=10..29} (t-p)^2
    float class_loss = 0.0f;
#pragma unroll
    for (int d = 10; d < 30; d++) {
        float df = t[d] - p[d];
        class_loss = fmaf(df, df, class_loss);
    }
    class_loss *= obj;

    // no-object confidence loss
    float dconf = t[4] - p[4];
    float conf_noobj = noobj * dconf * dconf;

    // responsibility via IoU of the two predicted boxes vs target box
    float iou1 = iou_f(t[0], t[1], t[2], t[3], p[0], p[1], p[2], p[3]);
    float iou2 = iou_f(t[0], t[1], t[2], t[3], p[5], p[6], p[7], p[8]);
    float resp1 = (iou1 > iou2) ? 1.0f : 0.0f;
    float m1 = obj * resp1;
    float m2 = obj * (1.0f - resp1);

    float e1 = iou1 - p[4];
    float e2 = iou2 - p[9];
    float conf_obj = m1 * e1 * e1 + m2 * e2 * e2;

    float dx1 = t[0] - p[0], dy1 = t[1] - p[1];
    float dx2 = t[0] - p[5], dy2 = t[1] - p[6];
    float xy = m1 * (dx1 * dx1 + dy1 * dy1) + m2 * (dx2 * dx2 + dy2 * dy2);

    float dw1 = t[2] - p[2], dh1 = t[3] - p[3];
    float dw2 = t[2] - p[7], dh2 = t[3] - p[8];
    float wh = m1 * (dw1 * dw1 + dh1 * dh1) + m2 * (dw2 * dw2 + dh2 * dh2);

    float cell = LAMBDA_COORD * (xy + wh) + conf_obj
               + LAMBDA_NOOBJ * conf_noobj + class_loss;

    // ---- deterministic block reduction in double ----
    double v = (double)cell;
#pragma unroll
    for (int off = 16; off > 0; off >>= 1)
        v += __shfl_down_sync(0xFFFFFFFFu, v, off);

    __shared__ double warp_sums[TPB / 32];
    const int lane = threadIdx.x & 31;
    const int wid  = threadIdx.x >> 5;
    if (lane == 0) warp_sums[wid] = v;
    __syncthreads();

    if (wid == 0) {
        double s = (lane < TPB / 32) ? warp_sums[lane] : 0.0;
#pragma unroll
        for (int off = 4; off > 0; off >>= 1)
            s += __shfl_down_sync(0xFFFFFFFFu, s, off);
        if (lane == 0) g_partials[blockIdx.x] = s;
    }
}

__global__ __launch_bounds__(1024) void yolo_finalize_kernel(float* __restrict__ out)
{
    double s = 0.0;
    for (int i = threadIdx.x; i < NBLK; i += 1024)
        s += g_partials[i];

#pragma unroll
    for (int off = 16; off > 0; off >>= 1)
        s += __shfl_down_sync(0xFFFFFFFFu, s, off);

    __shared__ double warp_sums[32];
    const int lane = threadIdx.x & 31;
    const int wid  = threadIdx.x >> 5;
    if (lane == 0) warp_sums[wid] = s;
    __syncthreads();

    if (wid == 0) {
        double t = (lane < 32) ? warp_sums[lane] : 0.0;
#pragma unroll
        for (int off = 16; off > 0; off >>= 1)
            t += __shfl_down_sync(0xFFFFFFFFu, t, off);
        if (lane == 0) out[0] = (float)(t / (double)B_SZ);
    }
}

extern "C" void kernel_launch(void* const* d_in, const int* in_sizes, int n_in,
                              void* d_out, int out_size)
{
    const float* y  = (const float*)d_in[0];
    const float* gt = (const float*)d_in[1];
    float* out = (float*)d_out;

    yolo_cell_kernel<<<NBLK, TPB>>>(y, gt);
    yolo_finalize_kernel<<<1, 1024>>>(out);
}